// round 1
// baseline (speedup 1.0000x reference)
#include <cuda_runtime.h>

// Casual_Conv1D: 31 chained Conv1d(1,1,k=2) == one 32-tap FIR + scalar bias.
//   c = conv(w_0, w_1, ..., w_30)   (length 32)
//   d = fold of bias through (w0+w1) gains
//   y[b,t] = sum_k c[k] * x[b, t+k] + d,  t in [0, 16353)

#define B_      128
#define L_      16384
#define NL_     31
#define LOUT_   (L_ - NL_)       // 16353
#define R_      16               // outputs per thread
#define TPB_    256
#define TILE_   (R_ * TPB_)      // 4096 outputs per block

__device__ float g_coef[32];
__device__ float g_bias;

// ---------------------------------------------------------------------------
// Kernel 1: compose the 31 k=2 filters into one 32-tap filter + bias.
// Warp-parallel: lane k owns coefficient c[k]; each layer is one shfl+fma.
// ---------------------------------------------------------------------------
__global__ void coef_kernel(const float* __restrict__ W,
                            const float* __restrict__ b) {
    int lane = threadIdx.x;  // 0..31
    float c = 0.0f;
    if (lane == 0) c = W[0];
    else if (lane == 1) c = W[1];
    float d = b[0];
    #pragma unroll
    for (int i = 1; i < NL_; ++i) {
        float w0 = W[2 * i];
        float w1 = W[2 * i + 1];
        float cp = __shfl_up_sync(0xFFFFFFFFu, c, 1);
        if (lane == 0) cp = 0.0f;
        c = w0 * c + w1 * cp;
        d = (w0 + w1) * d + b[i];
    }
    g_coef[lane] = c;
    if (lane == 0) g_bias = d;
}

// ---------------------------------------------------------------------------
// Kernel 2: FIR pass. Each block covers TILE_ outputs of one row; shared-memory
// tile of TILE_+31 inputs (halo deduped). Each thread produces R_=16 outputs
// in transposed-FIR form: every smem value read once, fanned into up to 16
// accumulators with compile-time-selected coefficients.
// ---------------------------------------------------------------------------
__global__ void __launch_bounds__(TPB_)
fir_kernel(const float* __restrict__ x, float* __restrict__ y) {
    __shared__ __align__(16) float s[TILE_ + 32];

    const int row   = blockIdx.y;
    const int tile0 = blockIdx.x * TILE_;
    const float* xr = x + (size_t)row * L_ + tile0;

    // cooperative vectorized load of TILE_+31 inputs (clipped at row end)
    const int nload = min(TILE_ + NL_, L_ - tile0);
    for (int i = threadIdx.x * 4; i < nload; i += TPB_ * 4) {
        if (i + 4 <= nload) {
            float4 v = *reinterpret_cast<const float4*>(xr + i);
            *reinterpret_cast<float4*>(s + i) = v;
        } else {
            for (int t = i; t < nload; ++t) s[t] = xr[t];
        }
    }
    __syncthreads();

    // broadcast coefficients into registers
    float c[32];
    #pragma unroll
    for (int k = 0; k < 32; ++k) c[k] = g_coef[k];
    const float bias = g_bias;

    const int o0   = threadIdx.x * R_;  // first output of this thread (in tile)
    const int gout = tile0 + o0;        // first output of this thread (in row)

    float acc[R_];
    #pragma unroll
    for (int j = 0; j < R_; ++j) acc[j] = bias;

    // transposed FIR: load each of the R_+31 inputs once, scatter into accs.
    #pragma unroll
    for (int m = 0; m < R_ + NL_; ++m) {
        float v = s[o0 + m];
        #pragma unroll
        for (int j = 0; j < R_; ++j) {
            if (m - j >= 0 && m - j < 32) {     // compile-time after unroll
                acc[j] += c[m - j] * v;
            }
        }
    }

    float* yr = y + (size_t)row * LOUT_;
    #pragma unroll
    for (int j = 0; j < R_; ++j) {
        if (gout + j < LOUT_) yr[gout + j] = acc[j];
    }
}

// ---------------------------------------------------------------------------
extern "C" void kernel_launch(void* const* d_in, const int* in_sizes, int n_in,
                              void* d_out, int out_size) {
    const float* x = (const float*)d_in[0];   // (128, 1, 16384) f32
    const float* W = (const float*)d_in[1];   // (31, 2) f32
    const float* b = (const float*)d_in[2];   // (31,)  f32
    float* y = (float*)d_out;                 // (128, 1, 16353) f32

    coef_kernel<<<1, 32>>>(W, b);

    dim3 grid((LOUT_ + TILE_ - 1) / TILE_, B_);  // (4, 128)
    fir_kernel<<<grid, TPB_>>>(x, y);
}

// round 2
// speedup vs baseline: 1.3718x; 1.3718x over previous
#include <cuda_runtime.h>

// Casual_Conv1D: 31 chained Conv1d(1,1,k=2) == one 32-tap FIR + scalar bias.
// Single fused kernel: warp 0 of each block composes the filter (31-step
// shfl recurrence), every thread computes 16 outputs from a register-resident
// 48-float window, outputs staged through conflict-free smem for coalesced STG.

#define B_    128
#define L_    16384
#define NL_   31
#define LOUT_ (L_ - NL_)          // 16353
#define R_    16                  // outputs per thread
#define TPB_  256
#define TILE_ (R_ * TPB_)         // 4096 outputs per block

__global__ void __launch_bounds__(TPB_)
fir_kernel(const float* __restrict__ x, const float* __restrict__ W,
           const float* __restrict__ b, float* __restrict__ y) {
    __shared__ float sc[32];
    __shared__ float sbias;
    __shared__ float sout[TILE_ + (TILE_ >> 4)];   // phys = i + (i>>4): stride-17

    const int tid   = threadIdx.x;
    const int row   = blockIdx.y;
    const int tile0 = blockIdx.x * TILE_;

    // ---- warp 0: compose 31 k=2 filters into 32-tap filter + scalar bias ----
    if (tid < 32) {
        float c = (tid == 0) ? W[0] : (tid == 1 ? W[1] : 0.0f);
        float d = b[0];
        #pragma unroll
        for (int i = 1; i < NL_; ++i) {
            float w0 = W[2 * i], w1 = W[2 * i + 1];
            float cp = __shfl_up_sync(0xFFFFFFFFu, c, 1);
            if (tid == 0) cp = 0.0f;
            c = w0 * c + w1 * cp;
            d = (w0 + w1) * d + b[i];
        }
        sc[tid] = c;
        if (tid == 0) sbias = d;
    }

    // ---- each thread: load its 48-float input window (12x LDG.128) ----
    const float* xrow = x + (size_t)row * L_;
    const int g0 = tile0 + tid * R_;               // 16-float aligned
    float xr[R_ + 32];
    #pragma unroll
    for (int i = 0; i < 12; ++i) {
        const int idx = g0 + 4 * i;
        float4 v;
        if (idx < L_ - 3) {
            v = *reinterpret_cast<const float4*>(xrow + idx);
        } else {
            v = make_float4(0.f, 0.f, 0.f, 0.f);   // only feeds masked outputs
        }
        xr[4 * i + 0] = v.x; xr[4 * i + 1] = v.y;
        xr[4 * i + 2] = v.z; xr[4 * i + 3] = v.w;
    }

    __syncthreads();   // sc / sbias ready (load completion tracked by regs)

    // ---- 512 fully-unrolled FMAs, 16 independent accumulator chains ----
    float acc[R_];
    #pragma unroll
    for (int j = 0; j < R_; ++j) acc[j] = 0.0f;

    #pragma unroll
    for (int k = 0; k < 32; ++k) {
        const float ck = sc[k];                    // LDS broadcast, 1 per 16 FMA
        #pragma unroll
        for (int j = 0; j < R_; ++j)
            acc[j] += ck * xr[j + k];
    }

    // ---- stage outputs in smem (conflict-free stride-17), coalesced STG ----
    const float bias = sbias;
    const int o0 = tid * R_;
    #pragma unroll
    for (int j = 0; j < R_; ++j) {
        const int i = o0 + j;
        sout[i + (i >> 4)] = acc[j] + bias;
    }
    __syncthreads();

    float* yrow = y + (size_t)row * LOUT_ + tile0;
    const int nvalid = min(TILE_, LOUT_ - tile0);
    for (int i = tid; i < nvalid; i += TPB_)
        yrow[i] = sout[i + (i >> 4)];
}

// ---------------------------------------------------------------------------
extern "C" void kernel_launch(void* const* d_in, const int* in_sizes, int n_in,
                              void* d_out, int out_size) {
    const float* x = (const float*)d_in[0];   // (128, 1, 16384) f32
    const float* W = (const float*)d_in[1];   // (31, 2) f32
    const float* b = (const float*)d_in[2];   // (31,)  f32
    float* y = (float*)d_out;                 // (128, 1, 16353) f32

    dim3 grid((LOUT_ + TILE_ - 1) / TILE_, B_);   // (4, 128)
    fir_kernel<<<grid, TPB_>>>(x, W, b, y);
}

// round 4
// speedup vs baseline: 1.4609x; 1.0649x over previous
#include <cuda_runtime.h>

// Casual_Conv1D: 31 chained Conv1d(1,1,k=2) == one 32-tap FIR + scalar bias.
// R4 (= R3 resubmit after infra failure): fma.rn.f32x2 packed math, rolling
// pair-ring (no big register window), per-warp coef composition (no barrier),
// 4 blocks/SM single wave, stride-17 padded smem for conflict-free access.

#define B_    128
#define L_    16384
#define NL_   31
#define LOUT_ (L_ - NL_)          // 16353
#define R_    16                  // outputs per thread
#define TPB_  256
#define TILE_ (R_ * TPB_)         // 4096 outputs per block
#define NIN_  (TILE_ + NL_)       // 4127 inputs per tile
#define PADN_ (NIN_ + (NIN_ >> 4) + 2)   // stride-17 padded input staging
#define PADO_ (TILE_ + (TILE_ >> 4))     // stride-17 padded output staging

typedef unsigned long long u64;

__device__ __forceinline__ u64 pk2(float lo, float hi) {
    u64 r; asm("mov.b64 %0, {%1, %2};" : "=l"(r) : "f"(lo), "f"(hi)); return r;
}
__device__ __forceinline__ void unpk2(u64 v, float& lo, float& hi) {
    asm("mov.b64 {%0, %1}, %2;" : "=f"(lo), "=f"(hi) : "l"(v));
}
__device__ __forceinline__ void ffma2(u64& d, u64 a, u64 b) {
    asm("fma.rn.f32x2 %0, %1, %2, %0;" : "+l"(d) : "l"(a), "l"(b));
}

__global__ void __launch_bounds__(TPB_, 4)
fir_kernel(const float* __restrict__ x, const float* __restrict__ W,
           const float* __restrict__ b, float* __restrict__ y) {
    __shared__ float sin[PADN_];
    __shared__ float sout[PADO_];

    const int tid   = threadIdx.x;
    const int lane  = tid & 31;
    const int row   = blockIdx.y;
    const int tile0 = blockIdx.x * TILE_;
    const float* xrow = x + (size_t)row * L_ + tile0;
    const bool last = (tile0 + NIN_ > L_);    // only last tile of a row

    // ---- stage input tile into padded smem (LDG.128 + scalar STS) ----
    // body: [0, 4096) for all tiles; float4 reads always in-bounds.
    #pragma unroll
    for (int j = 0; j < 4; ++j) {
        const int i = tid * 4 + j * (TPB_ * 4);
        float4 v = *reinterpret_cast<const float4*>(xrow + i);
        #pragma unroll
        for (int t = 0; t < 4; ++t) {
            const int ii = i + t;
            sin[ii + (ii >> 4)] = (&v.x)[t];
        }
    }
    // edge [4096, 4128): threads 0..7. For non-last tiles the float4 read at
    // 4124 touches x up to tile0+4127 <= 12319 < L (safe). Last tile: zeros.
    if (tid < 8) {
        const int i = 4096 + tid * 4;
        float4 v = last ? make_float4(0.f, 0.f, 0.f, 0.f)
                        : *reinterpret_cast<const float4*>(xrow + i);
        #pragma unroll
        for (int t = 0; t < 4; ++t) {
            const int ii = i + t;
            sin[ii + (ii >> 4)] = (&v.x)[t];
        }
    }

    // ---- per-warp filter composition (overlaps the LDG latency above) ----
    // lane k ends holding coefficient c[k]; every lane holds the bias d.
    float c = (lane == 0) ? W[0] : ((lane == 1) ? W[1] : 0.0f);
    float d = b[0];
    #pragma unroll
    for (int i = 1; i < NL_; ++i) {
        const float w0 = W[2 * i], w1 = W[2 * i + 1];
        float cp = __shfl_up_sync(0xFFFFFFFFu, c, 1);
        if (lane == 0) cp = 0.0f;
        c = w0 * c + w1 * cp;
        d = (w0 + w1) * d + b[i];
    }

    __syncthreads();

    // ---- rolling pair-ring FIR: 16 outputs/thread, fma.f32x2 ----
    const int o0 = tid * R_;     // local first output; lanes stride 16 ->
                                 // stride-17 physical -> conflict-free LDS
#define SIN(i_) sin[(i_) + ((i_) >> 4)]

    // init: 17 scalars -> 16 pairs pv[t] = {x[o0+t], x[o0+t+1]}, t=0..15
    u64 pv[16];
    float prev = SIN(o0);
    #pragma unroll
    for (int t = 0; t < 16; ++t) {
        float nx = SIN(o0 + t + 1);
        pv[t] = pk2(prev, nx);
        prev = nx;
    }
    float tailv = prev;           // == x[o0+16]

    u64 acc[8];
    const u64 bias2 = pk2(d, d);
    #pragma unroll
    for (int j = 0; j < 8; ++j) acc[j] = bias2;

    #pragma unroll
    for (int k = 0; k < 32; ++k) {
        const float ck = __shfl_sync(0xFFFFFFFFu, c, k);
        const u64 c2 = pk2(ck, ck);
        #pragma unroll
        for (int j2 = 0; j2 < 8; ++j2)
            ffma2(acc[j2], c2, pv[(k + 2 * j2) & 15]);
        if (k < 30) {                       // refill slot k with pair t=k+16
            float nx = SIN(o0 + k + 17);
            pv[k & 15] = pk2(tailv, nx);
            tailv = nx;
        }
    }

    // ---- stage outputs (stride-17, conflict-free), coalesced STG ----
    #pragma unroll
    for (int j2 = 0; j2 < 8; ++j2) {
        float lo, hi; unpk2(acc[j2], lo, hi);
        const int i0 = o0 + 2 * j2, i1 = i0 + 1;
        sout[i0 + (i0 >> 4)] = lo;
        sout[i1 + (i1 >> 4)] = hi;
    }
    __syncthreads();

    float* yrow = y + (size_t)row * LOUT_ + tile0;
    const int nvalid = min(TILE_, LOUT_ - tile0);
    for (int i = tid; i < nvalid; i += TPB_)
        yrow[i] = sout[i + (i >> 4)];
#undef SIN
}

// ---------------------------------------------------------------------------
extern "C" void kernel_launch(void* const* d_in, const int* in_sizes, int n_in,
                              void* d_out, int out_size) {
    const float* x = (const float*)d_in[0];   // (128, 1, 16384) f32
    const float* W = (const float*)d_in[1];   // (31, 2) f32
    const float* b = (const float*)d_in[2];   // (31,)  f32
    float* y = (float*)d_out;                 // (128, 1, 16353) f32

    dim3 grid((LOUT_ + TILE_ - 1) / TILE_, B_);   // (4, 128) = 512 blocks
    fir_kernel<<<grid, TPB_>>>(x, W, b, y);
}

// round 5
// speedup vs baseline: 1.4943x; 1.0229x over previous
#include <cuda_runtime.h>

// Casual_Conv1D: 31 chained Conv1d(1,1,k=2) == one 32-tap FIR + scalar bias.
// R5: no forced occupancy cap (R4's launch_bounds(,4) caused register spills:
// regs pinned at 64, L1 36%, ~3x instruction inflation). Coefficient pairs
// precomputed by warp 0 into smem (u64 broadcast LDS replaces per-warp shfl
// chain). Union smem buffer for input tile / output staging. fma.rn.f32x2.

#define B_    128
#define L_    16384
#define NL_   31
#define LOUT_ (L_ - NL_)          // 16353
#define R_    16                  // outputs per thread
#define TPB_  256
#define TILE_ (R_ * TPB_)         // 4096 outputs per block
#define NIN_  (TILE_ + NL_)       // 4127 inputs per tile
#define PADN_ (NIN_ + (NIN_ >> 4) + 2)   // stride-17 padded staging buffer

typedef unsigned long long u64;

__device__ __forceinline__ u64 pk2(float lo, float hi) {
    u64 r; asm("mov.b64 %0, {%1, %2};" : "=l"(r) : "f"(lo), "f"(hi)); return r;
}
__device__ __forceinline__ void unpk2(u64 v, float& lo, float& hi) {
    asm("mov.b64 {%0, %1}, %2;" : "=f"(lo), "=f"(hi) : "l"(v));
}
__device__ __forceinline__ void ffma2(u64& d, u64 a, u64 b) {
    asm("fma.rn.f32x2 %0, %1, %2, %0;" : "+l"(d) : "l"(a), "l"(b));
}

__global__ void __launch_bounds__(TPB_)
fir_kernel(const float* __restrict__ x, const float* __restrict__ W,
           const float* __restrict__ b, float* __restrict__ y) {
    __shared__ float sbuf[PADN_];     // input tile, later reused for outputs
    __shared__ u64   sc2[33];         // 32 coef pairs {c,c} + bias pair at [32]

    const int tid   = threadIdx.x;
    const int row   = blockIdx.y;
    const int tile0 = blockIdx.x * TILE_;
    const float* xrow = x + (size_t)row * L_ + tile0;
    const bool last = (tile0 + NIN_ > L_);    // only last tile of a row

    // ---- stage input tile [0,4096) into padded smem (LDG.128 + STS) ----
    #pragma unroll
    for (int j = 0; j < 4; ++j) {
        const int i = tid * 4 + j * (TPB_ * 4);
        float4 v = *reinterpret_cast<const float4*>(xrow + i);
        #pragma unroll
        for (int t = 0; t < 4; ++t) {
            const int ii = i + t;
            sbuf[ii + (ii >> 4)] = (&v.x)[t];
        }
    }
    // edge [4096,4128): warp 7 threads. Non-last tiles: reads reach
    // tile0+4127 <= 12319 < L (safe). Last tile: zero fill (masked outputs).
    if (tid >= 240 && tid < 248) {
        const int i = 4096 + (tid - 240) * 4;
        float4 v = last ? make_float4(0.f, 0.f, 0.f, 0.f)
                        : *reinterpret_cast<const float4*>(xrow + i);
        #pragma unroll
        for (int t = 0; t < 4; ++t) {
            const int ii = i + t;
            sbuf[ii + (ii >> 4)] = (&v.x)[t];
        }
    }

    // ---- warp 0 only: compose 31 k=2 filters -> 32-tap filter + bias ----
    if (tid < 32) {
        float c = (tid == 0) ? W[0] : ((tid == 1) ? W[1] : 0.0f);
        float d = b[0];
        #pragma unroll
        for (int i = 1; i < NL_; ++i) {
            const float w0 = W[2 * i], w1 = W[2 * i + 1];
            float cp = __shfl_up_sync(0xFFFFFFFFu, c, 1);
            if (tid == 0) cp = 0.0f;
            c = w0 * c + w1 * cp;
            d = (w0 + w1) * d + b[i];
        }
        sc2[tid] = pk2(c, c);
        if (tid == 0) sc2[32] = pk2(d, d);
    }
    __syncthreads();

    // ---- rolling pair-ring FIR: 16 outputs/thread, fma.rn.f32x2 ----
    const int o0 = tid * R_;       // stride-16 logical -> stride-17 physical
#define SIN(i_) sbuf[(i_) + ((i_) >> 4)]

    u64 pv[16];
    float prev = SIN(o0);
    #pragma unroll
    for (int t = 0; t < 16; ++t) {
        float nx = SIN(o0 + t + 1);
        pv[t] = pk2(prev, nx);
        prev = nx;
    }
    float tailv = prev;            // == x[o0+16]

    u64 acc[8];
    const u64 bias2 = sc2[32];
    #pragma unroll
    for (int j = 0; j < 8; ++j) acc[j] = bias2;

    #pragma unroll
    for (int k = 0; k < 32; ++k) {
        const u64 c2 = sc2[k];                    // LDS.64 broadcast
        #pragma unroll
        for (int j2 = 0; j2 < 8; ++j2)
            ffma2(acc[j2], c2, pv[(k + 2 * j2) & 15]);
        if (k < 30) {                             // refill slot with pair k+16
            float nx = SIN(o0 + k + 17);
            pv[k & 15] = pk2(tailv, nx);
            tailv = nx;
        }
    }

    // ---- restage outputs into (reused) padded smem, then coalesced STG ----
    __syncthreads();               // all SIN reads done before overwrite
    #pragma unroll
    for (int j2 = 0; j2 < 8; ++j2) {
        float lo, hi; unpk2(acc[j2], lo, hi);
        const int i0 = o0 + 2 * j2, i1 = i0 + 1;
        sbuf[i0 + (i0 >> 4)] = lo;
        sbuf[i1 + (i1 >> 4)] = hi;
    }
    __syncthreads();

    float* yrow = y + (size_t)row * LOUT_ + tile0;
    const int nvalid = min(TILE_, LOUT_ - tile0);
    if (nvalid == TILE_) {
        #pragma unroll
        for (int j = 0; j < R_; ++j) {
            const int i = tid + j * TPB_;
            yrow[i] = sbuf[i + (i >> 4)];
        }
    } else {
        for (int i = tid; i < nvalid; i += TPB_)
            yrow[i] = sbuf[i + (i >> 4)];
    }
#undef SIN
}

// ---------------------------------------------------------------------------
extern "C" void kernel_launch(void* const* d_in, const int* in_sizes, int n_in,
                              void* d_out, int out_size) {
    const float* x = (const float*)d_in[0];   // (128, 1, 16384) f32
    const float* W = (const float*)d_in[1];   // (31, 2) f32
    const float* b = (const float*)d_in[2];   // (31,)  f32
    float* y = (float*)d_out;                 // (128, 1, 16353) f32

    dim3 grid((LOUT_ + TILE_ - 1) / TILE_, B_);   // (4, 128) = 512 blocks
    fir_kernel<<<grid, TPB_>>>(x, W, b, y);
}

// round 6
// speedup vs baseline: 1.6701x; 1.1176x over previous
#include <cuda_runtime.h>

// Casual_Conv1D: 31 chained Conv1d(1,1,k=2) == one 32-tap FIR + scalar bias.
// R6: kill addressing overhead. All smem accesses use a once-computed base
// register + compile-time immediate offsets, exploiting o0=tid*16 alignment:
//   phys(o0+m) = 17*tid + (m + m/16)          (compute reads)
//   phys(tid*4 + j*1024 + t) = 4*tid + tid/4 + j*1088 + t   (prologue STS)
//   phys(o0+j) = 17*tid + j   (j<16)          (output staging STS)
//   phys(tid + j*256) = tid + tid/16 + j*272  (readout LDS)
// fma.rn.f32x2 packed math, 16-slot pair ring, warp0 coef compose.

#define B_    128
#define L_    16384
#define NL_   31
#define LOUT_ (L_ - NL_)          // 16353
#define R_    16
#define TPB_  256
#define TILE_ (R_ * TPB_)         // 4096
#define PADN_ 4392                // covers max phys index 4384

typedef unsigned long long u64;

__device__ __forceinline__ u64 pk2(float lo, float hi) {
    u64 r; asm("mov.b64 %0, {%1, %2};" : "=l"(r) : "f"(lo), "f"(hi)); return r;
}
__device__ __forceinline__ void unpk2(u64 v, float& lo, float& hi) {
    asm("mov.b64 {%0, %1}, %2;" : "=f"(lo), "=f"(hi) : "l"(v));
}
__device__ __forceinline__ void ffma2(u64& d, u64 a, u64 b) {
    asm("fma.rn.f32x2 %0, %1, %2, %0;" : "+l"(d) : "l"(a), "l"(b));
}

__global__ void __launch_bounds__(TPB_)
fir_kernel(const float* __restrict__ x, const float* __restrict__ W,
           const float* __restrict__ b, float* __restrict__ y) {
    __shared__ float sbuf[PADN_];     // input tile, reused for output staging
    __shared__ u64   sc2[33];         // 32 coef pairs {c,c}; bias pair at [32]

    const int tid   = threadIdx.x;
    const int row   = blockIdx.y;
    const int tile0 = blockIdx.x * TILE_;
    const float* xrow = x + (size_t)row * L_ + tile0;
    const bool last = (tile0 + TILE_ + NL_ > L_);   // last tile of each row

    // ---- prologue: stage [0,4096) via LDG.128; immediate-offset STS ----
    {
        float* sp = sbuf + tid * 4 + (tid >> 2);    // one-time base
        #pragma unroll
        for (int j = 0; j < 4; ++j) {
            float4 v = *reinterpret_cast<const float4*>(xrow + tid * 4 + j * 1024);
            sp[j * 1088 + 0] = v.x;
            sp[j * 1088 + 1] = v.y;
            sp[j * 1088 + 2] = v.z;
            sp[j * 1088 + 3] = v.w;
        }
    }
    // edge [4096,4128): warp 1. Non-last tiles: reads reach tile0+4127 <=
    // 12319 < L (safe). Last tile: zeros (feed only masked outputs).
    if (tid >= 32 && tid < 40) {
        const int e = tid - 32;
        float4 v = last ? make_float4(0.f, 0.f, 0.f, 0.f)
                        : *reinterpret_cast<const float4*>(xrow + 4096 + e * 4);
        float* sp = sbuf + 4352 + e * 4 + (e >> 2);
        sp[0] = v.x; sp[1] = v.y; sp[2] = v.z; sp[3] = v.w;
    }

    // ---- warp 0: compose 31 k=2 filters -> 32-tap filter + bias ----
    if (tid < 32) {
        float c = (tid == 0) ? W[0] : ((tid == 1) ? W[1] : 0.0f);
        float d = b[0];
        #pragma unroll
        for (int i = 1; i < NL_; ++i) {
            const float w0 = W[2 * i], w1 = W[2 * i + 1];
            float cp = __shfl_up_sync(0xFFFFFFFFu, c, 1);
            if (tid == 0) cp = 0.0f;
            c = w0 * c + w1 * cp;
            d = (w0 + w1) * d + b[i];
        }
        sc2[tid] = pk2(c, c);
        if (tid == 0) sc2[32] = pk2(d, d);
    }
    __syncthreads();

    // ---- rolling pair-ring FIR, all offsets compile-time ----
    const float* sp = sbuf + tid * 17;     // phys(o0+m) = 17*tid + m + m/16
#define XM(m_) sp[(m_) + ((m_) >> 4)]

    u64 pv[16];
    float prev = XM(0);
    #pragma unroll
    for (int t = 0; t < 16; ++t) {
        float nx = XM(t + 1);
        pv[t] = pk2(prev, nx);
        prev = nx;
    }
    float tailv = prev;                    // == x[o0+16]

    u64 acc[8];
    const u64 bias2 = sc2[32];
    #pragma unroll
    for (int j = 0; j < 8; ++j) acc[j] = bias2;

    #pragma unroll
    for (int k = 0; k < 32; ++k) {
        const u64 c2 = sc2[k];             // LDS.64 broadcast, imm offset
        #pragma unroll
        for (int j2 = 0; j2 < 8; ++j2)
            ffma2(acc[j2], c2, pv[(k + 2 * j2) & 15]);
        if (k < 30) {                      // refill with pair t = k+16
            float nx = XM(k + 17);
            pv[k & 15] = pk2(tailv, nx);
            tailv = nx;
        }
    }
#undef XM

    // ---- restage outputs (phys = 17*tid + j, j<16), coalesced writeout ----
    __syncthreads();                       // all reads done before overwrite
    {
        float* so = sbuf + tid * 17;
        #pragma unroll
        for (int j2 = 0; j2 < 8; ++j2) {
            float lo, hi; unpk2(acc[j2], lo, hi);
            so[2 * j2]     = lo;
            so[2 * j2 + 1] = hi;
        }
    }
    __syncthreads();

    float* yrow = y + (size_t)row * LOUT_ + tile0 + tid;
    const float* sr = sbuf + tid + (tid >> 4);   // phys(tid + j*256)
    if (!last) {
        #pragma unroll
        for (int j = 0; j < R_; ++j)
            yrow[j * 256] = sr[j * 272];
    } else {
        const int nvalid = LOUT_ - tile0;        // 4065
        #pragma unroll
        for (int j = 0; j < R_; ++j)
            if (tid + j * 256 < nvalid)
                yrow[j * 256] = sr[j * 272];
    }
}

// ---------------------------------------------------------------------------
extern "C" void kernel_launch(void* const* d_in, const int* in_sizes, int n_in,
                              void* d_out, int out_size) {
    const float* x = (const float*)d_in[0];   // (128, 1, 16384) f32
    const float* W = (const float*)d_in[1];   // (31, 2) f32
    const float* b = (const float*)d_in[2];   // (31,)  f32
    float* y = (float*)d_out;                 // (128, 1, 16353) f32

    dim3 grid((LOUT_ + TILE_ - 1) / TILE_, B_);   // (4, 128) = 512 blocks
    fir_kernel<<<grid, TPB_>>>(x, W, b, y);
}

// round 7
// speedup vs baseline: 1.9728x; 1.1813x over previous
#include <cuda_runtime.h>

// Casual_Conv1D: 31 chained Conv1d(1,1,k=2) == one 32-tap FIR + scalar bias.
// R7: latency-bound fix. TPB 256->128, TILE 4096->2048, 1024 blocks ->
// ~9 resident blocks/SM (reg-limited) = ~36 warps/SM with 9 independent
// barrier groups; one wave. Instruction structure from R6 kept: immediate
// offset smem addressing, fma.rn.f32x2 pair-ring, warp0 coef compose.

#define B_    128
#define L_    16384
#define NL_   31
#define LOUT_ (L_ - NL_)          // 16353
#define R_    16
#define TPB_  128
#define TILE_ (R_ * TPB_)         // 2048
#define PADN_ 2212                // covers max phys index 2207

typedef unsigned long long u64;

__device__ __forceinline__ u64 pk2(float lo, float hi) {
    u64 r; asm("mov.b64 %0, {%1, %2};" : "=l"(r) : "f"(lo), "f"(hi)); return r;
}
__device__ __forceinline__ void unpk2(u64 v, float& lo, float& hi) {
    asm("mov.b64 {%0, %1}, %2;" : "=f"(lo), "=f"(hi) : "l"(v));
}
__device__ __forceinline__ void ffma2(u64& d, u64 a, u64 b) {
    asm("fma.rn.f32x2 %0, %1, %2, %0;" : "+l"(d) : "l"(a), "l"(b));
}

__global__ void __launch_bounds__(TPB_)
fir_kernel(const float* __restrict__ x, const float* __restrict__ W,
           const float* __restrict__ b, float* __restrict__ y) {
    __shared__ float sbuf[PADN_];     // input tile, reused for output staging
    __shared__ u64   sc2[33];         // 32 coef pairs {c,c}; bias pair at [32]

    const int tid   = threadIdx.x;
    const int row   = blockIdx.y;
    const int tile0 = blockIdx.x * TILE_;
    const float* xrow = x + (size_t)row * L_ + tile0;
    const bool last = (tile0 + TILE_ + NL_ > L_);   // last tile of each row

    // ---- prologue: stage [0,2048) via 4x LDG.128; immediate-offset STS ----
    // phys(tid*4 + 512j + t) = tid*4 + tid/4 + 544j + t
    {
        float* sp = sbuf + tid * 4 + (tid >> 2);
        #pragma unroll
        for (int j = 0; j < 4; ++j) {
            float4 v = *reinterpret_cast<const float4*>(xrow + tid * 4 + j * 512);
            sp[j * 544 + 0] = v.x;
            sp[j * 544 + 1] = v.y;
            sp[j * 544 + 2] = v.z;
            sp[j * 544 + 3] = v.w;
        }
    }
    // edge [2048,2080): warp 1 threads 32..39. Non-last tiles read at most
    // tile0+2079 <= 12288+2079 < 16384 (safe). Last tile: zeros (masked out).
    if (tid >= 32 && tid < 40) {
        const int e = tid - 32;
        float4 v = last ? make_float4(0.f, 0.f, 0.f, 0.f)
                        : *reinterpret_cast<const float4*>(xrow + 2048 + e * 4);
        float* sp = sbuf + 2176 + e * 4 + (e >> 2);
        sp[0] = v.x; sp[1] = v.y; sp[2] = v.z; sp[3] = v.w;
    }

    // ---- warp 0: compose 31 k=2 filters -> 32-tap filter + bias ----
    if (tid < 32) {
        float c = (tid == 0) ? W[0] : ((tid == 1) ? W[1] : 0.0f);
        float d = b[0];
        #pragma unroll
        for (int i = 1; i < NL_; ++i) {
            const float w0 = W[2 * i], w1 = W[2 * i + 1];
            float cp = __shfl_up_sync(0xFFFFFFFFu, c, 1);
            if (tid == 0) cp = 0.0f;
            c = w0 * c + w1 * cp;
            d = (w0 + w1) * d + b[i];
        }
        sc2[tid] = pk2(c, c);
        if (tid == 0) sc2[32] = pk2(d, d);
    }
    __syncthreads();

    // ---- rolling pair-ring FIR, all smem offsets compile-time ----
    const float* sp = sbuf + tid * 17;     // phys(o0+m) = 17*tid + m + m/16
#define XM(m_) sp[(m_) + ((m_) >> 4)]

    u64 pv[16];
    float prev = XM(0);
    #pragma unroll
    for (int t = 0; t < 16; ++t) {
        float nx = XM(t + 1);
        pv[t] = pk2(prev, nx);
        prev = nx;
    }
    float tailv = prev;                    // == x[o0+16]

    u64 acc[8];
    const u64 bias2 = sc2[32];
    #pragma unroll
    for (int j = 0; j < 8; ++j) acc[j] = bias2;

    #pragma unroll
    for (int k = 0; k < 32; ++k) {
        const u64 c2 = sc2[k];             // LDS.64 broadcast, imm offset
        #pragma unroll
        for (int j2 = 0; j2 < 8; ++j2)
            ffma2(acc[j2], c2, pv[(k + 2 * j2) & 15]);
        if (k < 30) {                      // refill with pair t = k+16
            float nx = XM(k + 17);
            pv[k & 15] = pk2(tailv, nx);
            tailv = nx;
        }
    }
#undef XM

    // ---- restage outputs (phys = 17*tid + j, j<16), coalesced writeout ----
    __syncthreads();                       // all reads done before overwrite
    {
        float* so = sbuf + tid * 17;
        #pragma unroll
        for (int j2 = 0; j2 < 8; ++j2) {
            float lo, hi; unpk2(acc[j2], lo, hi);
            so[2 * j2]     = lo;
            so[2 * j2 + 1] = hi;
        }
    }
    __syncthreads();

    // readout: i = tid + 128j, phys = tid + tid/16 + 136j
    float* yrow = y + (size_t)row * LOUT_ + tile0 + tid;
    const float* sr = sbuf + tid + (tid >> 4);
    if (!last) {
        #pragma unroll
        for (int j = 0; j < R_; ++j)
            yrow[j * 128] = sr[j * 136];
    } else {
        const int nvalid = LOUT_ - tile0;  // 2017
        #pragma unroll
        for (int j = 0; j < R_; ++j)
            if (tid + j * 128 < nvalid)
                yrow[j * 128] = sr[j * 136];
    }
}

// ---------------------------------------------------------------------------
extern "C" void kernel_launch(void* const* d_in, const int* in_sizes, int n_in,
                              void* d_out, int out_size) {
    const float* x = (const float*)d_in[0];   // (128, 1, 16384) f32
    const float* W = (const float*)d_in[1];   // (31, 2) f32
    const float* b = (const float*)d_in[2];   // (31,)  f32
    float* y = (float*)d_out;                 // (128, 1, 16353) f32

    dim3 grid((LOUT_ + TILE_ - 1) / TILE_, B_);   // (8, 128) = 1024 blocks
    fir_kernel<<<grid, TPB_>>>(x, W, b, y);
}